// round 6
// baseline (speedup 1.0000x reference)
#include <cuda_runtime.h>
#include <cuda_bf16.h>
#include <cstdint>

// ============================================================================
// FreqLinear via legacy tensor path (mma.sync bf16) — tcgen05 unavailable on
// this toolchain's .target sm_103.
//
//   out[m,o] = sum_K Y'[m,K] * idx_f[o,K] + const[m] + bias[o]
//   Y'[m, blk*8+k] = (c_range[k]/255) * sum_t x[m, blk*16+t] * B[k,t]
//   const[m]       = sum_k c_min[k] * sum_blk (sum_t x*B[k,t])
//
// Y' split into two bf16 limbs (hi+lo); idx (0..255) exact in bf16.
// GEMM: CTA tile M=128 (o) x N=128 (m), K chunks of 64, 8 warps (4x2),
// warp tile 32x64, mma.m16n8k16, ldmatrix feeds, cp.async for B limbs,
// inline int32->bf16 conversion for A, double-buffered smem.
// ============================================================================

// ---------------- constants ----------------
static constexpr int IN_F   = 4096;
static constexpr int OUT_F  = 8192;
static constexpr int MROWS  = 256;
static constexpr int KTOT   = 2048;
static constexpr int K_CHUNK = 64;
static constexpr int NITER  = KTOT / K_CHUNK;   // 32
static constexpr int M_TILE = 128;              // o per CTA
static constexpr int N_TILE = 128;              // m per CTA

// smem layout (dynamic)
#define SM_A(b)   ((b) * 16384)             // A tiles (idx bf16): 2 x 16 KB
#define SM_BH(b)  (32768 + (b) * 16384)     // Yhi tiles: 2 x 16 KB
#define SM_BL(b)  (65536 + (b) * 16384)     // Ylo tiles: 2 x 16 KB
#define SM_CONST  98304                     // 128 floats
static constexpr int SMEM_TOTAL = 98304 + 512;

#define SWZ(o) ((o) ^ (((o) >> 3) & 0x70))  // SW128: bits[6:4] ^= bits[9:7]

// ---------------- scratch (__device__ globals; no allocation allowed) -------
__device__ __align__(16) __nv_bfloat16 g_Yhi[MROWS * KTOT];  // 1 MB
__device__ __align__(16) __nv_bfloat16 g_Ylo[MROWS * KTOT];  // 1 MB
__device__ float g_const[MROWS];

// ---------------- small asm helpers ----------------
__device__ __forceinline__ uint32_t smem_to_u32(const void* p) {
    uint32_t a;
    asm("{ .reg .u64 t; cvta.to.shared.u64 t, %1; cvt.u32.u64 %0, t; }" : "=r"(a) : "l"(p));
    return a;
}

__device__ __forceinline__ void ldmatrix_x4(uint32_t* r, uint32_t addr) {
    asm volatile("ldmatrix.sync.aligned.m8n8.x4.shared.b16 {%0,%1,%2,%3}, [%4];"
                 : "=r"(r[0]), "=r"(r[1]), "=r"(r[2]), "=r"(r[3]) : "r"(addr));
}

__device__ __forceinline__ void mma_16816(float* d, const uint32_t* a,
                                          uint32_t b0, uint32_t b1) {
    asm volatile(
        "mma.sync.aligned.m16n8k16.row.col.f32.bf16.bf16.f32 "
        "{%0,%1,%2,%3}, {%4,%5,%6,%7}, {%8,%9}, {%0,%1,%2,%3};"
        : "+f"(d[0]), "+f"(d[1]), "+f"(d[2]), "+f"(d[3])
        : "r"(a[0]), "r"(a[1]), "r"(a[2]), "r"(a[3]), "r"(b0), "r"(b1));
}

__device__ __forceinline__ void cp_async16(uint32_t smem_addr, const void* gptr) {
    asm volatile("cp.async.cg.shared.global [%0], [%1], 16;"
                 :: "r"(smem_addr), "l"(gptr) : "memory");
}
#define CP_COMMIT() asm volatile("cp.async.commit_group;" ::: "memory")
#define CP_WAIT_ALL() asm volatile("cp.async.wait_group 0;" ::: "memory")

__device__ __forceinline__ uint32_t pack_bf16_pair(int a, int b) {
    uint32_t l = (uint32_t)__bfloat16_as_ushort(__float2bfloat16_rn((float)a));
    uint32_t h = (uint32_t)__bfloat16_as_ushort(__float2bfloat16_rn((float)b));
    return l | (h << 16);
}

// ---------------- Kernel 1: DCT of x, limb split, c_min constant ------------
__global__ __launch_bounds__(256, 1) void freql_prep_kernel(
    const float* __restrict__ x, const float* __restrict__ c_min,
    const float* __restrict__ c_range) {
    __shared__ float xs[IN_F];
    __shared__ float Bsm[8][16];
    __shared__ float red[256];

    const int m = blockIdx.x;
    const int tid = threadIdx.x;

    for (int i = tid; i < IN_F; i += 256) xs[i] = x[(size_t)m * IN_F + i];
    if (tid < 128) {
        int k = tid >> 4, j = tid & 15;
        float s = (k == 0) ? 0.25f : 0.35355339059327373f;  // sqrt(2/16), k=0: /sqrt2
        Bsm[k][j] = cospif((j + 0.5f) * (float)k * (1.0f / 16.0f)) * s;
    }
    __syncthreads();

    const int blk = tid;  // one 16-sample block per thread
    float acc[8];
#pragma unroll
    for (int k = 0; k < 8; k++) acc[k] = 0.0f;
#pragma unroll
    for (int j = 0; j < 16; j++) {
        float xv = xs[blk * 16 + j];
#pragma unroll
        for (int k = 0; k < 8; k++) acc[k] += xv * Bsm[k][j];
    }

    float cmv[8], crv[8];
#pragma unroll
    for (int k = 0; k < 8; k++) { cmv[k] = c_min[k]; crv[k] = c_range[k]; }

    float cst = 0.0f;
    struct alignas(16) B8 { __nv_bfloat16 h[8]; };
    B8 hi, lo;
#pragma unroll
    for (int k = 0; k < 8; k++) {
        cst += cmv[k] * acc[k];
        float v = acc[k] * (crv[k] * (1.0f / 255.0f));
        __nv_bfloat16 h = __float2bfloat16_rn(v);
        float resid = v - __bfloat162float(h);
        hi.h[k] = h;
        lo.h[k] = __float2bfloat16_rn(resid);
    }
    *(uint4*)&g_Yhi[(size_t)m * KTOT + blk * 8] = *(uint4*)&hi;
    *(uint4*)&g_Ylo[(size_t)m * KTOT + blk * 8] = *(uint4*)&lo;

    red[tid] = cst;
    __syncthreads();
    for (int s = 128; s > 0; s >>= 1) {
        if (tid < s) red[tid] += red[tid + s];
        __syncthreads();
    }
    if (tid == 0) g_const[m] = red[0];
}

// ---------------- Kernel 2: bf16 mma.sync GEMM ----------------
__global__ __launch_bounds__(256, 1) void freql_gemm_kernel(
    const int* __restrict__ idx, const float* __restrict__ bias,
    float* __restrict__ out) {
    extern __shared__ char smem[];
    const uint32_t sa = smem_to_u32(smem);
    const int tid = threadIdx.x;
    const int wid = tid >> 5;
    const int lid = tid & 31;
    const int wo = wid & 3;          // warp o-tile (4)
    const int wm = wid >> 2;         // warp m-tile (2)
    const int o_base = blockIdx.x * M_TILE;
    const int m_base = blockIdx.y * N_TILE;

    // cache const[m] for this m-tile
    if (tid < 128) ((float*)(smem + SM_CONST))[tid] = g_const[m_base + tid];

    const int* arow = idx + (size_t)o_base * KTOT;

    // per-thread chunk mapping (shared by A convert and B cp.async):
    // chunk = tid + q*256 -> row r = chunk>>3 (0..127), 16B col c8 = chunk&7
    int4 va[8];

    auto ldgA = [&](int kb) {
#pragma unroll
        for (int q = 0; q < 4; q++) {
            int chunk = tid + q * 256;
            int r = chunk >> 3, c8 = chunk & 7;
            const int4* s = (const int4*)(arow + (size_t)r * KTOT + kb + c8 * 8);
            va[q * 2] = s[0];
            va[q * 2 + 1] = s[1];
        }
    };
    auto stsA = [&](int buf) {
#pragma unroll
        for (int q = 0; q < 4; q++) {
            int chunk = tid + q * 256;
            int r = chunk >> 3, c8 = chunk & 7;
            uint4 p;
            p.x = pack_bf16_pair(va[q * 2].x, va[q * 2].y);
            p.y = pack_bf16_pair(va[q * 2].z, va[q * 2].w);
            p.z = pack_bf16_pair(va[q * 2 + 1].x, va[q * 2 + 1].y);
            p.w = pack_bf16_pair(va[q * 2 + 1].z, va[q * 2 + 1].w);
            uint32_t off = (uint32_t)(r * 128 + c8 * 16);
            *(uint4*)(smem + SM_A(buf) + SWZ(off)) = p;
        }
    };
    auto cpB = [&](int it, int buf) {
        int kb = it * K_CHUNK;
#pragma unroll
        for (int q = 0; q < 4; q++) {
            int chunk = tid + q * 256;
            int r = chunk >> 3, c8 = chunk & 7;
            uint32_t off = SWZ((uint32_t)(r * 128 + c8 * 16));
            size_t g = (size_t)(m_base + r) * KTOT + kb + c8 * 8;
            cp_async16(sa + SM_BH(buf) + off, g_Yhi + g);
            cp_async16(sa + SM_BL(buf) + off, g_Ylo + g);
        }
    };

    // accumulators: warp tile 32(o) x 64(m) = 2 m16-tiles x 8 n8-tiles
    float acc[2][8][4];
#pragma unroll
    for (int i = 0; i < 2; i++)
#pragma unroll
        for (int j = 0; j < 8; j++)
#pragma unroll
            for (int c = 0; c < 4; c++) acc[i][j][c] = 0.0f;

    // ldmatrix lane address components
    const int a_row = lid & 15;
    const int a_cb  = (lid >> 4) * 16;
    const int b_row = (lid & 7) + ((lid >> 4) << 3);
    const int b_cb  = ((lid >> 3) & 1) * 16;

    // prologue: fill buffer 0
    ldgA(0);
    cpB(0, 0);
    CP_COMMIT();
    stsA(0);
    CP_WAIT_ALL();
    __syncthreads();

    for (int it = 0; it < NITER; ++it) {
        const int cur = it & 1, nxt = cur ^ 1;
        const bool pf = (it + 1 < NITER);
        if (pf) {
            ldgA((it + 1) * K_CHUNK);
            cpB(it + 1, nxt);
            CP_COMMIT();
        }

        // ---- compute on buffer `cur` ----
#pragma unroll
        for (int s = 0; s < 4; s++) {
            uint32_t afr[2][4];
#pragma unroll
            for (int mt = 0; mt < 2; mt++) {
                uint32_t off = (uint32_t)((wo * 32 + mt * 16 + a_row) * 128 + s * 32 + a_cb);
                ldmatrix_x4(afr[mt], sa + SM_A(cur) + SWZ(off));
            }
#pragma unroll
            for (int limb = 0; limb < 2; limb++) {
                const uint32_t bbase = sa + (limb ? SM_BL(cur) : SM_BH(cur));
#pragma unroll
                for (int ng = 0; ng < 4; ng++) {
                    uint32_t bfr[4];
                    uint32_t off = (uint32_t)((wm * 64 + ng * 16 + b_row) * 128 + s * 32 + b_cb);
                    ldmatrix_x4(bfr, bbase + SWZ(off));
#pragma unroll
                    for (int mt = 0; mt < 2; mt++) {
                        mma_16816(acc[mt][ng * 2 + 0], afr[mt], bfr[0], bfr[1]);
                        mma_16816(acc[mt][ng * 2 + 1], afr[mt], bfr[2], bfr[3]);
                    }
                }
            }
        }

        if (pf) {
            stsA(nxt);
            CP_WAIT_ALL();
            __syncthreads();
        }
    }

    // ---- epilogue: out[m, o] = acc + const[m] + bias[o] ----
    const float* scst = (const float*)(smem + SM_CONST);
    const int t4 = lid >> 2;
    const int m_lo = (lid & 3) * 2;

    float bv[2][2];
#pragma unroll
    for (int mt = 0; mt < 2; mt++)
#pragma unroll
        for (int rr = 0; rr < 2; rr++)
            bv[mt][rr] = __ldg(bias + o_base + wo * 32 + mt * 16 + rr * 8 + t4);

#pragma unroll
    for (int mt = 0; mt < 2; mt++) {
#pragma unroll
        for (int nidx = 0; nidx < 8; nidx++) {
            int ml = wm * 64 + nidx * 8 + m_lo;
            float c0 = scst[ml], c1 = scst[ml + 1];
            size_t g0 = (size_t)(m_base + ml) * OUT_F;
            size_t g1 = g0 + OUT_F;
#pragma unroll
            for (int rr = 0; rr < 2; rr++) {
                int o = o_base + wo * 32 + mt * 16 + rr * 8 + t4;
                out[g0 + o] = acc[mt][nidx][rr * 2 + 0] + c0 + bv[mt][rr];
                out[g1 + o] = acc[mt][nidx][rr * 2 + 1] + c1 + bv[mt][rr];
            }
        }
    }
}

// ---------------- launch ----------------
extern "C" void kernel_launch(void* const* d_in, const int* in_sizes, int n_in,
                              void* d_out, int out_size) {
    const float* x       = (const float*)d_in[0];
    const int*   idx     = (const int*)d_in[1];
    const float* c_min   = (const float*)d_in[2];
    const float* c_range = (const float*)d_in[3];
    const float* bias    = (const float*)d_in[4];
    float* out = (float*)d_out;

    cudaFuncSetAttribute(freql_gemm_kernel,
                         cudaFuncAttributeMaxDynamicSharedMemorySize, SMEM_TOTAL);

    freql_prep_kernel<<<MROWS, 256>>>(x, c_min, c_range);
    freql_gemm_kernel<<<dim3(OUT_F / M_TILE, MROWS / N_TILE), 256, SMEM_TOTAL>>>(idx, bias, out);
}

// round 7
// speedup vs baseline: 1.2941x; 1.2941x over previous
#include <cuda_runtime.h>
#include <cuda_fp16.h>
#include <cstdint>

// ============================================================================
// FreqLinear via mma.sync fp16 (single limb, scaled x256).
//
//   out[m,o] = (1/256) * sum_K (256*Y'[m,K]) * idx_f[o,K] + const[m] + bias[o]
//   Y'[m, blk*8+k] = (c_range[k]/255) * sum_t x[m, blk*16+t] * B[k,t]
//   const[m]       = sum_k c_min[k] * sum_blk (sum_t x*B[k,t])
//
// idx (0..255) exact in fp16; 256*Y' ~ N(0,1)*[0.1,1.1] -> comfortably normal.
// GEMM: CTA tile M=128 (o) x N=128 (m), K chunks of 64, 16 warps (4x4),
// warp tile 32x32, mma.m16n8k16.f32.f16.f16.f32, ldmatrix feeds,
// cp.async for B, inline int32->fp16 conversion for A, double-buffered smem.
// ============================================================================

// ---------------- constants ----------------
static constexpr int IN_F   = 4096;
static constexpr int OUT_F  = 8192;
static constexpr int MROWS  = 256;
static constexpr int KTOT   = 2048;
static constexpr int K_CHUNK = 64;
static constexpr int NITER  = KTOT / K_CHUNK;   // 32
static constexpr int M_TILE = 128;              // o per CTA
static constexpr int N_TILE = 128;              // m per CTA

// smem layout (dynamic):
//   [0 .. 65536)    pipeline: A 2x16KB, B 2x16KB   (reused as 128x132 f32 staging)
//   [67584 .. )     const cache: 128 floats
//   [68096 .. )     bias cache: 128 floats
#define SM_A(b)   ((b) * 16384)
#define SM_B(b)   (32768 + (b) * 16384)
#define SM_CONST  67584
#define SM_BIAS   68096
static constexpr int SMEM_TOTAL = 68640;

#define SWZ(o) ((o) ^ (((o) >> 3) & 0x70))  // SW128: bits[6:4] ^= bits[9:7]

// ---------------- scratch (__device__ globals; no allocation allowed) -------
__device__ __align__(16) __half g_Yh[MROWS * KTOT];  // 1 MB, holds 256*Y'
__device__ float g_const[MROWS];

// ---------------- small asm helpers ----------------
__device__ __forceinline__ uint32_t smem_to_u32(const void* p) {
    uint32_t a;
    asm("{ .reg .u64 t; cvta.to.shared.u64 t, %1; cvt.u32.u64 %0, t; }" : "=r"(a) : "l"(p));
    return a;
}

__device__ __forceinline__ void ldmatrix_x4(uint32_t* r, uint32_t addr) {
    asm volatile("ldmatrix.sync.aligned.m8n8.x4.shared.b16 {%0,%1,%2,%3}, [%4];"
                 : "=r"(r[0]), "=r"(r[1]), "=r"(r[2]), "=r"(r[3]) : "r"(addr));
}

__device__ __forceinline__ void mma_16816(float* d, const uint32_t* a,
                                          uint32_t b0, uint32_t b1) {
    asm volatile(
        "mma.sync.aligned.m16n8k16.row.col.f32.f16.f16.f32 "
        "{%0,%1,%2,%3}, {%4,%5,%6,%7}, {%8,%9}, {%0,%1,%2,%3};"
        : "+f"(d[0]), "+f"(d[1]), "+f"(d[2]), "+f"(d[3])
        : "r"(a[0]), "r"(a[1]), "r"(a[2]), "r"(a[3]), "r"(b0), "r"(b1));
}

__device__ __forceinline__ void cp_async16(uint32_t smem_addr, const void* gptr) {
    asm volatile("cp.async.cg.shared.global [%0], [%1], 16;"
                 :: "r"(smem_addr), "l"(gptr) : "memory");
}
#define CP_COMMIT() asm volatile("cp.async.commit_group;" ::: "memory")
#define CP_WAIT_ALL() asm volatile("cp.async.wait_group 0;" ::: "memory")

__device__ __forceinline__ uint32_t pack_fp16_pair(int a, int b) {
    uint32_t l = (uint32_t)__half_as_ushort(__float2half_rn((float)a));
    uint32_t h = (uint32_t)__half_as_ushort(__float2half_rn((float)b));
    return l | (h << 16);
}

// ---------------- Kernel 1: DCT of x, fp16 (x256), c_min constant -----------
__global__ __launch_bounds__(256, 1) void freql_prep_kernel(
    const float* __restrict__ x, const float* __restrict__ c_min,
    const float* __restrict__ c_range) {
    __shared__ float xs[IN_F];
    __shared__ float Bsm[8][16];
    __shared__ float warp_red[8];

    const int m = blockIdx.x;
    const int tid = threadIdx.x;

    for (int i = tid; i < IN_F; i += 256) xs[i] = x[(size_t)m * IN_F + i];
    if (tid < 128) {
        int k = tid >> 4, j = tid & 15;
        float s = (k == 0) ? 0.25f : 0.35355339059327373f;  // sqrt(2/16), k=0: /sqrt2
        Bsm[k][j] = cospif((j + 0.5f) * (float)k * (1.0f / 16.0f)) * s;
    }
    __syncthreads();

    const int blk = tid;  // one 16-sample block per thread
    float acc[8];
#pragma unroll
    for (int k = 0; k < 8; k++) acc[k] = 0.0f;
#pragma unroll
    for (int j = 0; j < 16; j++) {
        float xv = xs[blk * 16 + j];
#pragma unroll
        for (int k = 0; k < 8; k++) acc[k] += xv * Bsm[k][j];
    }

    float cmv[8], crv[8];
#pragma unroll
    for (int k = 0; k < 8; k++) { cmv[k] = c_min[k]; crv[k] = c_range[k]; }

    float cst = 0.0f;
    struct alignas(16) H8 { __half h[8]; };
    H8 hv;
#pragma unroll
    for (int k = 0; k < 8; k++) {
        cst += cmv[k] * acc[k];
        float v = acc[k] * (crv[k] * (256.0f / 255.0f));  // store 256*Y'
        hv.h[k] = __float2half_rn(v);
    }
    *(uint4*)&g_Yh[(size_t)m * KTOT + blk * 8] = *(uint4*)&hv;

    // warp shuffle reduction of the c_min term (deterministic order)
#pragma unroll
    for (int s = 16; s > 0; s >>= 1) cst += __shfl_down_sync(0xFFFFFFFFu, cst, s);
    if ((tid & 31) == 0) warp_red[tid >> 5] = cst;
    __syncthreads();
    if (tid == 0) {
        float t = 0.0f;
#pragma unroll
        for (int w = 0; w < 8; w++) t += warp_red[w];
        g_const[m] = t;
    }
}

// ---------------- Kernel 2: fp16 mma.sync GEMM ----------------
__global__ __launch_bounds__(512, 1) void freql_gemm_kernel(
    const int* __restrict__ idx, const float* __restrict__ bias,
    float* __restrict__ out) {
    extern __shared__ char smem[];
    const uint32_t sa = smem_to_u32(smem);
    const int tid = threadIdx.x;
    const int wid = tid >> 5;
    const int lid = tid & 31;
    const int wo = wid & 3;          // warp o-tile (4 x 32)
    const int wm = wid >> 2;         // warp m-tile (4 x 32)
    const int o_base = blockIdx.x * M_TILE;
    const int m_base = blockIdx.y * N_TILE;

    // cache const[m] and bias[o] for this tile
    if (tid < 128) {
        ((float*)(smem + SM_CONST))[tid] = g_const[m_base + tid];
        ((float*)(smem + SM_BIAS))[tid] = __ldg(bias + o_base + tid);
    }

    const int* arow = idx + (size_t)o_base * KTOT;

    // per-thread chunk mapping (A convert + B cp.async):
    // chunk = tid + q*512 (q=0,1) -> row r = chunk>>3 (0..127), 16B col c8 = chunk&7
    int4 va[4];

    auto ldgA = [&](int kb) {
#pragma unroll
        for (int q = 0; q < 2; q++) {
            int chunk = tid + q * 512;
            int r = chunk >> 3, c8 = chunk & 7;
            const int4* s = (const int4*)(arow + (size_t)r * KTOT + kb + c8 * 8);
            va[q * 2] = s[0];
            va[q * 2 + 1] = s[1];
        }
    };
    auto stsA = [&](int buf) {
#pragma unroll
        for (int q = 0; q < 2; q++) {
            int chunk = tid + q * 512;
            int r = chunk >> 3, c8 = chunk & 7;
            uint4 p;
            p.x = pack_fp16_pair(va[q * 2].x, va[q * 2].y);
            p.y = pack_fp16_pair(va[q * 2].z, va[q * 2].w);
            p.z = pack_fp16_pair(va[q * 2 + 1].x, va[q * 2 + 1].y);
            p.w = pack_fp16_pair(va[q * 2 + 1].z, va[q * 2 + 1].w);
            uint32_t off = (uint32_t)(r * 128 + c8 * 16);
            *(uint4*)(smem + SM_A(buf) + SWZ(off)) = p;
        }
    };
    auto cpB = [&](int it, int buf) {
        int kb = it * K_CHUNK;
#pragma unroll
        for (int q = 0; q < 2; q++) {
            int chunk = tid + q * 512;
            int r = chunk >> 3, c8 = chunk & 7;
            uint32_t off = SWZ((uint32_t)(r * 128 + c8 * 16));
            size_t g = (size_t)(m_base + r) * KTOT + kb + c8 * 8;
            cp_async16(sa + SM_B(buf) + off, g_Yh + g);
        }
    };

    // accumulators: warp tile 32(o) x 32(m) = 2 m16-tiles x 4 n8-tiles
    float acc[2][4][4];
#pragma unroll
    for (int i = 0; i < 2; i++)
#pragma unroll
        for (int j = 0; j < 4; j++)
#pragma unroll
            for (int c = 0; c < 4; c++) acc[i][j][c] = 0.0f;

    // ldmatrix lane address components
    const int a_row = lid & 15;
    const int a_cb  = (lid >> 4) * 16;
    const int b_row = (lid & 7) + ((lid >> 4) << 3);
    const int b_cb  = ((lid >> 3) & 1) * 16;

    // prologue: fill buffer 0
    ldgA(0);
    cpB(0, 0);
    CP_COMMIT();
    stsA(0);
    CP_WAIT_ALL();
    __syncthreads();

    for (int it = 0; it < NITER; ++it) {
        const int cur = it & 1, nxt = cur ^ 1;
        const bool pf = (it + 1 < NITER);
        if (pf) {
            ldgA((it + 1) * K_CHUNK);
            cpB(it + 1, nxt);
            CP_COMMIT();
        }

        // ---- compute on buffer `cur` ----
#pragma unroll
        for (int s = 0; s < 4; s++) {
            uint32_t afr[2][4];
#pragma unroll
            for (int mt = 0; mt < 2; mt++) {
                uint32_t off = (uint32_t)((wo * 32 + mt * 16 + a_row) * 128 + s * 32 + a_cb);
                ldmatrix_x4(afr[mt], sa + SM_A(cur) + SWZ(off));
            }
#pragma unroll
            for (int ng = 0; ng < 2; ng++) {
                uint32_t bfr[4];
                uint32_t off = (uint32_t)((wm * 32 + ng * 16 + b_row) * 128 + s * 32 + b_cb);
                ldmatrix_x4(bfr, sa + SM_B(cur) + SWZ(off));
#pragma unroll
                for (int mt = 0; mt < 2; mt++) {
                    mma_16816(acc[mt][ng * 2 + 0], afr[mt], bfr[0], bfr[1]);
                    mma_16816(acc[mt][ng * 2 + 1], afr[mt], bfr[2], bfr[3]);
                }
            }
        }

        if (pf) {
            stsA(nxt);
            CP_WAIT_ALL();
            __syncthreads();
        }
    }

    // ---- epilogue: stage (acc/256 + const[m]) into smem [m][132], then
    //      coalesced float4 stores of out[m,o] += bias[o] ----
    __syncthreads();  // everyone done reading A/B smem
    {
        const float* scst = (const float*)(smem + SM_CONST);
        float* stg = (float*)smem;
        const int t4 = lid >> 2;
        const float inv256 = 1.0f / 256.0f;
#pragma unroll
        for (int mt = 0; mt < 2; mt++) {
#pragma unroll
            for (int nidx = 0; nidx < 4; nidx++) {
#pragma unroll
                for (int c = 0; c < 4; c++) {
                    int o = wo * 32 + mt * 16 + ((c >> 1) << 3) + t4;
                    int mm = wm * 32 + nidx * 8 + (lid & 3) * 2 + (c & 1);
                    stg[mm * 132 + o] = acc[mt][nidx][c] * inv256 + scst[mm];
                }
            }
        }
    }
    __syncthreads();
    {
        const float* stg = (const float*)smem;
        const float* sbias = (const float*)(smem + SM_BIAS);
        const int o4 = (tid & 31) * 4;
        float4 bv;
        bv.x = sbias[o4]; bv.y = sbias[o4 + 1]; bv.z = sbias[o4 + 2]; bv.w = sbias[o4 + 3];
#pragma unroll
        for (int p = 0; p < 8; p++) {
            int mm = p * 16 + (tid >> 5);
            float4 v = *(const float4*)(stg + mm * 132 + o4);
            v.x += bv.x; v.y += bv.y; v.z += bv.z; v.w += bv.w;
            *(float4*)(out + (size_t)(m_base + mm) * OUT_F + o_base + o4) = v;
        }
    }
}

// ---------------- launch ----------------
extern "C" void kernel_launch(void* const* d_in, const int* in_sizes, int n_in,
                              void* d_out, int out_size) {
    const float* x       = (const float*)d_in[0];
    const int*   idx     = (const int*)d_in[1];
    const float* c_min   = (const float*)d_in[2];
    const float* c_range = (const float*)d_in[3];
    const float* bias    = (const float*)d_in[4];
    float* out = (float*)d_out;

    cudaFuncSetAttribute(freql_gemm_kernel,
                         cudaFuncAttributeMaxDynamicSharedMemorySize, SMEM_TOTAL);

    freql_prep_kernel<<<MROWS, 256>>>(x, c_min, c_range);
    freql_gemm_kernel<<<dim3(OUT_F / M_TILE, MROWS / N_TILE), 512, SMEM_TOTAL>>>(idx, bias, out);
}